// round 8
// baseline (speedup 1.0000x reference)
#include <cuda_runtime.h>
#include <cuda_bf16.h>

#define NX 192
#define NY 192
#define NZ 192
#define NXY (NX * NY)

#define VEC 2                    // float2 per thread in x
#define SEGW (32 * VEC)          // 64 x per warp
#define WYD 4                    // 4 warps/CTA, 1 y-row each
#define NTHREADS 128
#define ZCHUNK 32                // even (2-phase slot rotation)
#define GXB (NX / SEGW)          // 3
#define GYB (NY / WYD)           // 48
#define GZB (NZ / ZCHUNK)        // 6
#define NBLOCKS (GXB * GYB * GZB) // 864 (single wave at 6 CTAs/SM)

#define FULLMASK 0xFFFFFFFFu

__device__ double g_acc = 0.0;
__device__ unsigned int g_done = 0;

// One image plane, this thread's float2 at (x2, y): per-element
//   gx = sum_{dy in -1..1} [v(x+1)-v(x-1)]
//   gy = rowsum(y+1) - rowsum(y-1)
//   b  = 3x3 box sum
// x-neighbors loaded directly ([P-4]/[P+8], mostly L1 hits thanks to the
// y-overlap); volume-edge lanes predicate the load off and SEL the clamp.
__device__ __forceinline__ void plane_pass(
    const float* __restrict__ base, const int* __restrict__ co,
    bool pl, bool pr,
    float& gx0, float& gx1, float& gy0, float& gy1, float& b0, float& b1)
{
    float h0[3], h1[3], d0s = 0.f, d1s = 0.f;
#pragma unroll
    for (int r = 0; r < 3; ++r) {
        const float* p = base + co[r];
        float2 v = *reinterpret_cast<const float2*>(p);
        float l  = pl ? p[-1] : v.x;   // predicated LDG + SEL (no OOB when off)
        float rr = pr ? p[2]  : v.y;
        float s = v.x + v.y;
        h0[r] = l + s;
        h1[r] = s + rr;
        d0s += v.y - l;
        d1s += rr - v.x;
    }
    gx0 = d0s;
    gx1 = d1s;
    gy0 = h0[2] - h0[0];
    gy1 = h1[2] - h1[0];
    b0  = h0[0] + h0[1] + h0[2];
    b1  = h1[0] + h1[1] + h1[2];
}

// One z-step for output plane z0+kk. Slot `o` = stats(z-1), slot `m` = stats(z).
// Fresh stats(z+1) computed into temporaries, then written over slot `o`.
#define STEP(o, m, kk)                                                        \
    {                                                                         \
        int zq = z0 + (kk) + 1;                                               \
        int gz = zq > NZ - 1 ? NZ - 1 : zq;                                   \
        float ngxI0, ngxI1, ngyI0, ngyI1, nbI0, nbI1;                         \
        float ngxJ0, ngxJ1, ngyJ0, ngyJ1, nbJ0, nbJ1;                         \
        plane_pass(I + (size_t)gz * NXY, co, pl, pr,                          \
                   ngxI0, ngxI1, ngyI0, ngyI1, nbI0, nbI1);                   \
        plane_pass(J + (size_t)gz * NXY, co, pl, pr,                          \
                   ngxJ0, ngxJ1, ngyJ0, ngyJ1, nbJ0, nbJ1);                   \
        float2 m2 = *reinterpret_cast<const float2*>(mp);                     \
        {                                                                     \
            float Ix = gxI[o][0] + gxI[m][0] + ngxI0;                         \
            float Iy = gyI[o][0] + gyI[m][0] + ngyI0;                         \
            float Iz = nbI0 - bI[o][0];                                       \
            float Jx = gxJ[o][0] + gxJ[m][0] + ngxJ0;                         \
            float Jy = gyJ[o][0] + gyJ[m][0] + ngyJ0;                         \
            float Jz = nbJ0 - bJ[o][0];                                       \
            float ssi  = fmaf(Ix, Ix, fmaf(Iy, Iy, Iz * Iz));                 \
            float ssj  = fmaf(Jx, Jx, fmaf(Jy, Jy, Jz * Jz));                 \
            float sdot = fmaf(Ix, Jx, fmaf(Iy, Jy, Iz * Jz));                 \
            float imag = fmaf(0.25f, ssi, 0.01f);                             \
            float jmag = fmaf(0.25f, ssj, 0.01f);                             \
            float ngf  = __fdividef(0.0625f * sdot * sdot, imag * jmag);      \
            acc = fmaf(1.0f - ngf, m2.x, acc);                                \
        }                                                                     \
        {                                                                     \
            float Ix = gxI[o][1] + gxI[m][1] + ngxI1;                         \
            float Iy = gyI[o][1] + gyI[m][1] + ngyI1;                         \
            float Iz = nbI1 - bI[o][1];                                       \
            float Jx = gxJ[o][1] + gxJ[m][1] + ngxJ1;                         \
            float Jy = gyJ[o][1] + gyJ[m][1] + ngyJ1;                         \
            float Jz = nbJ1 - bJ[o][1];                                       \
            float ssi  = fmaf(Ix, Ix, fmaf(Iy, Iy, Iz * Iz));                 \
            float ssj  = fmaf(Jx, Jx, fmaf(Jy, Jy, Jz * Jz));                 \
            float sdot = fmaf(Ix, Jx, fmaf(Iy, Jy, Iz * Jz));                 \
            float imag = fmaf(0.25f, ssi, 0.01f);                             \
            float jmag = fmaf(0.25f, ssj, 0.01f);                             \
            float ngf  = __fdividef(0.0625f * sdot * sdot, imag * jmag);      \
            acc = fmaf(1.0f - ngf, m2.y, acc);                                \
        }                                                                     \
        gxI[o][0] = ngxI0; gxI[o][1] = ngxI1;                                 \
        gyI[o][0] = ngyI0; gyI[o][1] = ngyI1;                                 \
        bI[o][0]  = nbI0;  bI[o][1]  = nbI1;                                  \
        gxJ[o][0] = ngxJ0; gxJ[o][1] = ngxJ1;                                 \
        gyJ[o][0] = ngyJ0; gyJ[o][1] = ngyJ1;                                 \
        bJ[o][0]  = nbJ0;  bJ[o][1]  = nbJ1;                                  \
        mp += NXY;                                                            \
    }

__global__ __launch_bounds__(NTHREADS, 6)
void ngf_kernel(const float* __restrict__ I,
                const float* __restrict__ J,
                const float* __restrict__ M,
                float* __restrict__ out)
{
    __shared__ float warp_sums[WYD];

    const int lane = threadIdx.x;
    const int wy   = threadIdx.y;
    const int tid  = wy * 32 + lane;
    const int seg  = blockIdx.x;
    const int x2   = seg * SEGW + lane * VEC;
    const int y    = blockIdx.y * WYD + wy;
    const int z0   = blockIdx.z * ZCHUNK;

    const bool pl = (x2 > 0);           // left neighbor exists
    const bool pr = (x2 < NX - VEC);    // right neighbor of v.y exists

    // Combined (clamped y-row + x) element offsets, constant across z
    int co[3];
#pragma unroll
    for (int r = 0; r < 3; ++r) {
        int gy = y - 1 + r;
        gy = gy < 0 ? 0 : (gy > NY - 1 ? NY - 1 : gy);
        co[r] = gy * NX + x2;
    }

    // 2-slot rolling z-state: [0]/[1] alternate as (z-1)/(z) per step phase
    float gxI[2][VEC], gyI[2][VEC], bI[2][VEC];
    float gxJ[2][VEC], gyJ[2][VEC], bJ[2][VEC];

    // Prologue: plane z0-1 (clamped) -> slot 0, plane z0 -> slot 1
    {
        int gzm = z0 - 1 < 0 ? 0 : z0 - 1;
        plane_pass(I + (size_t)gzm * NXY, co, pl, pr,
                   gxI[0][0], gxI[0][1], gyI[0][0], gyI[0][1], bI[0][0], bI[0][1]);
        plane_pass(J + (size_t)gzm * NXY, co, pl, pr,
                   gxJ[0][0], gxJ[0][1], gyJ[0][0], gyJ[0][1], bJ[0][0], bJ[0][1]);
        plane_pass(I + (size_t)z0 * NXY, co, pl, pr,
                   gxI[1][0], gxI[1][1], gyI[1][0], gyI[1][1], bI[1][0], bI[1][1]);
        plane_pass(J + (size_t)z0 * NXY, co, pl, pr,
                   gxJ[1][0], gxJ[1][1], gyJ[1][0], gyJ[1][1], bJ[1][0], bJ[1][1]);
    }

    float acc = 0.0f;
    const float* mp = M + (size_t)z0 * NXY + co[1];  // co[1] == y*NX + x2

    // ZCHUNK steps, 2-phase unrolled: slots alternate (0,1) -> (1,0)
    for (int kb = 0; kb < ZCHUNK; kb += 2) {
        STEP(0, 1, kb + 0)
        STEP(1, 0, kb + 1)
    }

    // Block reduction
#pragma unroll
    for (int off = 16; off > 0; off >>= 1)
        acc += __shfl_xor_sync(FULLMASK, acc, off);
    if (lane == 0) warp_sums[wy] = acc;
    __syncthreads();

    if (tid == 0) {
        float v = warp_sums[0] + warp_sums[1] + warp_sums[2] + warp_sums[3];
        atomicAdd(&g_acc, (double)v);
        __threadfence();
        unsigned prev = atomicAdd(&g_done, 1u);
        if (prev == NBLOCKS - 1) {
            // All other blocks' g_acc adds are fenced before their g_done
            // increments, so an atomic read here sees the full sum.
            double tot = atomicAdd(&g_acc, 0.0);
            out[0] = (float)(tot * (1.0 / (double)((long long)NX * NY * NZ)));
            g_acc = 0.0;       // reset for next replay (deterministic)
            __threadfence();
            g_done = 0;
        }
    }
}

extern "C" void kernel_launch(void* const* d_in, const int* in_sizes, int n_in,
                              void* d_out, int out_size) {
    const float* I = (const float*)d_in[0];
    const float* J = (const float*)d_in[1];
    const float* M = (const float*)d_in[2];
    float* out = (float*)d_out;

    dim3 block(32, WYD, 1);
    dim3 grid(GXB, GYB, GZB);   // 3 x 48 x 6 = 864 CTAs
    ngf_kernel<<<grid, block>>>(I, J, M, out);
}

// round 9
// speedup vs baseline: 1.1293x; 1.1293x over previous
#include <cuda_runtime.h>
#include <cuda_bf16.h>

#define NX 192
#define NY 192
#define NZ 192
#define NXY (NX * NY)

#define VEC 2                    // float2 per thread in x
#define SEGW (32 * VEC)          // 64 x per warp
#define WYD 3                    // 3 warps/CTA
#define YPT 2                    // output y-rows per thread
#define ROWS (YPT + 2)           // 4 input rows per plane
#define NTHREADS (32 * WYD)      // 96
#define ZCHUNK 16                // even (2-phase slot rotation)
#define GXB (NX / SEGW)          // 3
#define GYB (NY / (WYD * YPT))   // 32
#define GZB (NZ / ZCHUNK)        // 12
#define NBLOCKS (GXB * GYB * GZB) // 1152 (single wave at 8 CTAs/SM)

#define FULLMASK 0xFFFFFFFFu

__device__ double g_acc = 0.0;
__device__ unsigned int g_done = 0;

// One image plane: 4 rows (y-1..y+2), float2 per row. Emits per output row
// i in {0,1}, per element e in {0,1}:
//   gx = sum_{dy} [v(x+1)-v(x-1)],  gy = rowsum(y+1)-rowsum(y-1),  b = 3x3 box
// x-neighbors via warp shuffles; segment-edge lanes patch via predicated LDG.
__device__ __forceinline__ void plane_pass(
    const float* __restrict__ base, const int* __restrict__ co,
    int lane, int segL, int segR,
    float gx[YPT][VEC], float gy[YPT][VEC], float b[YPT][VEC])
{
    float h0[ROWS], h1[ROWS], d0[ROWS], d1[ROWS];
#pragma unroll
    for (int r = 0; r < ROWS; ++r) {
        const float* p = base + co[r];
        float2 v = *reinterpret_cast<const float2*>(p);
        float l  = __shfl_up_sync(FULLMASK, v.y, 1);
        float rr = __shfl_down_sync(FULLMASK, v.x, 1);
        if (lane == 0)  l  = segL ? v.x : p[-1];
        if (lane == 31) rr = segR ? v.y : p[2];
        float s = v.x + v.y;
        h0[r] = l + s;
        h1[r] = s + rr;
        d0[r] = v.y - l;
        d1[r] = rr - v.x;
    }
#pragma unroll
    for (int i = 0; i < YPT; ++i) {
        gx[i][0] = d0[i] + d0[i + 1] + d0[i + 2];
        gx[i][1] = d1[i] + d1[i + 1] + d1[i + 2];
        gy[i][0] = h0[i + 2] - h0[i];
        gy[i][1] = h1[i + 2] - h1[i];
        b[i][0]  = h0[i] + h0[i + 1] + h0[i + 2];
        b[i][1]  = h1[i] + h1[i + 1] + h1[i + 2];
    }
}

// One z-step for output plane z0+kk. Slot `o` = stats(z-1), `m` = stats(z).
// Fresh stats(z+1) go to temporaries, then overwrite slot `o`.
#define STEP(o, m, kk)                                                        \
    {                                                                         \
        int zq = z0 + (kk) + 1;                                               \
        int gz = zq > NZ - 1 ? NZ - 1 : zq;                                   \
        float nxI[YPT][VEC], nyI[YPT][VEC], nbI[YPT][VEC];                    \
        float nxJ[YPT][VEC], nyJ[YPT][VEC], nbJ[YPT][VEC];                    \
        plane_pass(I + (size_t)gz * NXY, co, lane, segL, segR, nxI, nyI, nbI);\
        plane_pass(J + (size_t)gz * NXY, co, lane, segL, segR, nxJ, nyJ, nbJ);\
        float2 m0 = *reinterpret_cast<const float2*>(mp + co[1]);             \
        float2 m1 = *reinterpret_cast<const float2*>(mp + co[2]);             \
        const float mm[YPT][VEC] = {{m0.x, m0.y}, {m1.x, m1.y}};              \
        _Pragma("unroll")                                                     \
        for (int i = 0; i < YPT; ++i) {                                       \
            _Pragma("unroll")                                                 \
            for (int e = 0; e < VEC; ++e) {                                   \
                float Ix = gxI[o][i][e] + gxI[m][i][e] + nxI[i][e];           \
                float Iy = gyI[o][i][e] + gyI[m][i][e] + nyI[i][e];           \
                float Iz = nbI[i][e] - bI[o][i][e];                           \
                float Jx = gxJ[o][i][e] + gxJ[m][i][e] + nxJ[i][e];           \
                float Jy = gyJ[o][i][e] + gyJ[m][i][e] + nyJ[i][e];           \
                float Jz = nbJ[i][e] - bJ[o][i][e];                           \
                float ssi  = fmaf(Ix, Ix, fmaf(Iy, Iy, Iz * Iz));             \
                float ssj  = fmaf(Jx, Jx, fmaf(Jy, Jy, Jz * Jz));             \
                float sdot = fmaf(Ix, Jx, fmaf(Iy, Jy, Iz * Jz));             \
                float imag = fmaf(0.25f, ssi, 0.01f);                         \
                float jmag = fmaf(0.25f, ssj, 0.01f);                         \
                float ngf  = __fdividef(0.0625f * sdot * sdot, imag * jmag);  \
                acc = fmaf(1.0f - ngf, mm[i][e], acc);                        \
            }                                                                 \
        }                                                                     \
        _Pragma("unroll")                                                     \
        for (int i = 0; i < YPT; ++i) {                                       \
            _Pragma("unroll")                                                 \
            for (int e = 0; e < VEC; ++e) {                                   \
                gxI[o][i][e] = nxI[i][e]; gyI[o][i][e] = nyI[i][e];           \
                bI[o][i][e]  = nbI[i][e];                                     \
                gxJ[o][i][e] = nxJ[i][e]; gyJ[o][i][e] = nyJ[i][e];           \
                bJ[o][i][e]  = nbJ[i][e];                                     \
            }                                                                 \
        }                                                                     \
        mp += NXY;                                                            \
    }

__global__ __launch_bounds__(NTHREADS, 8)
void ngf_kernel(const float* __restrict__ I,
                const float* __restrict__ J,
                const float* __restrict__ M,
                float* __restrict__ out)
{
    __shared__ float warp_sums[WYD];

    const int lane = threadIdx.x;
    const int wy   = threadIdx.y;
    const int tid  = wy * 32 + lane;
    const int seg  = blockIdx.x;
    const int x2   = seg * SEGW + lane * VEC;
    const int yb   = blockIdx.y * (WYD * YPT) + wy * YPT; // first output row
    const int z0   = blockIdx.z * ZCHUNK;
    const int segL = (seg == 0);
    const int segR = (seg == GXB - 1);

    // Clamped (row + x) offsets for input rows yb-1 .. yb+2, constant over z.
    // co[1], co[2] are the (unclamped, always valid) output rows.
    int co[ROWS];
#pragma unroll
    for (int r = 0; r < ROWS; ++r) {
        int gy = yb - 1 + r;
        gy = gy < 0 ? 0 : (gy > NY - 1 ? NY - 1 : gy);
        co[r] = gy * NX + x2;
    }

    // 2-slot rolling z-state
    float gxI[2][YPT][VEC], gyI[2][YPT][VEC], bI[2][YPT][VEC];
    float gxJ[2][YPT][VEC], gyJ[2][YPT][VEC], bJ[2][YPT][VEC];

    // Prologue: plane z0-1 (clamped) -> slot 0, plane z0 -> slot 1
    {
        int gzm = z0 - 1 < 0 ? 0 : z0 - 1;
        plane_pass(I + (size_t)gzm * NXY, co, lane, segL, segR, gxI[0], gyI[0], bI[0]);
        plane_pass(J + (size_t)gzm * NXY, co, lane, segL, segR, gxJ[0], gyJ[0], bJ[0]);
        plane_pass(I + (size_t)z0  * NXY, co, lane, segL, segR, gxI[1], gyI[1], bI[1]);
        plane_pass(J + (size_t)z0  * NXY, co, lane, segL, segR, gxJ[1], gyJ[1], bJ[1]);
    }

    float acc = 0.0f;
    const float* mp = M + (size_t)z0 * NXY;

    // ZCHUNK steps, 2-phase unrolled: slots alternate (0,1) -> (1,0)
    for (int kb = 0; kb < ZCHUNK; kb += 2) {
        STEP(0, 1, kb + 0)
        STEP(1, 0, kb + 1)
    }

    // Block reduction (3 warps)
#pragma unroll
    for (int off = 16; off > 0; off >>= 1)
        acc += __shfl_xor_sync(FULLMASK, acc, off);
    if (lane == 0) warp_sums[wy] = acc;
    __syncthreads();

    if (tid == 0) {
        float v = warp_sums[0] + warp_sums[1] + warp_sums[2];
        atomicAdd(&g_acc, (double)v);
        __threadfence();
        unsigned prev = atomicAdd(&g_done, 1u);
        if (prev == NBLOCKS - 1) {
            // All other blocks' g_acc adds are fenced before their g_done
            // increments, so an atomic read here sees the full sum.
            double tot = atomicAdd(&g_acc, 0.0);
            out[0] = (float)(tot * (1.0 / (double)((long long)NX * NY * NZ)));
            g_acc = 0.0;       // reset for next replay (deterministic)
            __threadfence();
            g_done = 0;
        }
    }
}

extern "C" void kernel_launch(void* const* d_in, const int* in_sizes, int n_in,
                              void* d_out, int out_size) {
    const float* I = (const float*)d_in[0];
    const float* J = (const float*)d_in[1];
    const float* M = (const float*)d_in[2];
    float* out = (float*)d_out;

    dim3 block(32, WYD, 1);
    dim3 grid(GXB, GYB, GZB);   // 3 x 32 x 12 = 1152 CTAs
    ngf_kernel<<<grid, block>>>(I, J, M, out);
}

// round 10
// speedup vs baseline: 1.3219x; 1.1706x over previous
#include <cuda_runtime.h>
#include <cuda_bf16.h>

#define NX 192
#define NY 192
#define NZ 192
#define NXY (NX * NY)

#define WYD 4                    // warps/CTA, each owns YPT output rows
#define YPT 2
#define ROWS (YPT + 2)           // 4 input rows per plane
#define NTHREADS 128
#define ZCHUNK 32
#define GXB (NX / 32)            // 6
#define GYB (NY / (WYD * YPT))   // 24
#define GZB (NZ / ZCHUNK)        // 6
#define NBLOCKS (GXB * GYB * GZB) // 864 (single wave at 6 CTAs/SM)

#define FULLMASK 0xFFFFFFFFu

__device__ double g_acc = 0.0;
__device__ unsigned int g_done = 0;

// From preloaded row values v[4] (+ edge patches e[4]), compute 2-output-row
// plane stats: gx = sum_dy (v_r - v_l), gy = rowsum(y+1)-rowsum(y-1), b = 3x3.
__device__ __forceinline__ void rows_stats(
    const float* __restrict__ v, const float* __restrict__ e, int lane,
    float* __restrict__ gx, float* __restrict__ gy, float* __restrict__ b)
{
    float h[ROWS], d[ROWS];
#pragma unroll
    for (int r = 0; r < ROWS; ++r) {
        float l  = __shfl_up_sync(FULLMASK, v[r], 1);
        float rr = __shfl_down_sync(FULLMASK, v[r], 1);
        if (lane == 0)  l  = e[r];
        if (lane == 31) rr = e[r];
        h[r] = l + v[r] + rr;
        d[r] = rr - l;
    }
    float td = d[1] + d[2];
    gx[0] = td + d[0];
    gx[1] = td + d[3];
    float th = h[1] + h[2];
    b[0] = th + h[0];
    b[1] = th + h[3];
    gy[0] = h[2] - h[0];
    gy[1] = h[3] - h[1];
}

// One z-step for output plane z0+kk. Slot `o` = stats(z-1), `m` = stats(z).
// All loads issued up front (high MLP), then stats, combine, state overwrite.
#define STEP(o, m, kk)                                                        \
    {                                                                         \
        int zq = z0 + (kk) + 1;                                               \
        int gz = zq > NZ - 1 ? NZ - 1 : zq;                                   \
        size_t zoff = (size_t)gz * NXY;                                       \
        const float* pI = I + zoff;                                           \
        const float* pJ = J + zoff;                                           \
        float vI[ROWS], vJ[ROWS], eI[ROWS], eJ[ROWS];                         \
        _Pragma("unroll")                                                     \
        for (int r = 0; r < ROWS; ++r) vI[r] = pI[co[r]];                     \
        _Pragma("unroll")                                                     \
        for (int r = 0; r < ROWS; ++r) vJ[r] = pJ[co[r]];                     \
        float m0 = mp[0];                                                     \
        float m1 = mp[NX];                                                    \
        if (edge) {                                                           \
            _Pragma("unroll")                                                 \
            for (int r = 0; r < ROWS; ++r) {                                  \
                eI[r] = pI[co[r] + dxe];                                      \
                eJ[r] = pJ[co[r] + dxe];                                      \
            }                                                                 \
        }                                                                     \
        float nxI[YPT], nyI[YPT], nbI[YPT];                                   \
        float nxJ[YPT], nyJ[YPT], nbJ[YPT];                                   \
        rows_stats(vI, eI, lane, nxI, nyI, nbI);                              \
        rows_stats(vJ, eJ, lane, nxJ, nyJ, nbJ);                              \
        const float mm[YPT] = {m0, m1};                                       \
        _Pragma("unroll")                                                     \
        for (int i = 0; i < YPT; ++i) {                                       \
            float Ix = gxI[o][i] + gxI[m][i] + nxI[i];                        \
            float Iy = gyI[o][i] + gyI[m][i] + nyI[i];                        \
            float Iz = nbI[i] - bI[o][i];                                     \
            float Jx = gxJ[o][i] + gxJ[m][i] + nxJ[i];                        \
            float Jy = gyJ[o][i] + gyJ[m][i] + nyJ[i];                        \
            float Jz = nbJ[i] - bJ[o][i];                                     \
            float ssi  = fmaf(Ix, Ix, fmaf(Iy, Iy, Iz * Iz));                 \
            float ssj  = fmaf(Jx, Jx, fmaf(Jy, Jy, Jz * Jz));                 \
            float sdot = fmaf(Ix, Jx, fmaf(Iy, Jy, Iz * Jz));                 \
            float imag = ssi + 0.04f;   /* folded: ngf = sdot^2/(imag*jmag) */\
            float jmag = ssj + 0.04f;                                         \
            float ngf  = __fdividef(sdot * sdot, imag * jmag);                \
            acc = fmaf(1.0f - ngf, mm[i], acc);                               \
        }                                                                     \
        _Pragma("unroll")                                                     \
        for (int i = 0; i < YPT; ++i) {                                       \
            gxI[o][i] = nxI[i]; gyI[o][i] = nyI[i]; bI[o][i] = nbI[i];        \
            gxJ[o][i] = nxJ[i]; gyJ[o][i] = nyJ[i]; bJ[o][i] = nbJ[i];        \
        }                                                                     \
        mp += NXY;                                                            \
    }

__global__ __launch_bounds__(NTHREADS, 6)
void ngf_kernel(const float* __restrict__ I,
                const float* __restrict__ J,
                const float* __restrict__ M,
                float* __restrict__ out)
{
    __shared__ float warp_sums[WYD];

    const int lane = threadIdx.x;
    const int wy   = threadIdx.y;
    const int tid  = wy * 32 + lane;
    const int x    = blockIdx.x * 32 + lane;
    const int yb   = blockIdx.y * (WYD * YPT) + wy * YPT;  // first output row
    const int z0   = blockIdx.z * ZCHUNK;

    const bool edge = (lane == 0) || (lane == 31);
    // Per-lane x-neighbor offset for edge lanes (0 at volume border = clamp:
    // the edge load then returns v itself, which is the replicated pad value)
    int dxe = 0;
    if (lane == 0)  dxe = (x > 0)      ? -1 : 0;
    if (lane == 31) dxe = (x < NX - 1) ? +1 : 0;

    // Clamped (row*NX + x) offsets for input rows yb-1 .. yb+2
    int co[ROWS];
#pragma unroll
    for (int r = 0; r < ROWS; ++r) {
        int gy = yb - 1 + r;
        gy = gy < 0 ? 0 : (gy > NY - 1 ? NY - 1 : gy);
        co[r] = gy * NX + x;
    }

    // 2-slot rolling z-state
    float gxI[2][YPT], gyI[2][YPT], bI[2][YPT];
    float gxJ[2][YPT], gyJ[2][YPT], bJ[2][YPT];

    // Prologue: plane z0-1 (clamped) -> slot 0, plane z0 -> slot 1
    {
        int gzm = z0 - 1 < 0 ? 0 : z0 - 1;
#pragma unroll
        for (int s = 0; s < 2; ++s) {
            size_t zoff = (size_t)(s == 0 ? gzm : z0) * NXY;
            const float* pI = I + zoff;
            const float* pJ = J + zoff;
            float vI[ROWS], vJ[ROWS], eI[ROWS], eJ[ROWS];
#pragma unroll
            for (int r = 0; r < ROWS; ++r) { vI[r] = pI[co[r]]; vJ[r] = pJ[co[r]]; }
            if (edge) {
#pragma unroll
                for (int r = 0; r < ROWS; ++r) {
                    eI[r] = pI[co[r] + dxe];
                    eJ[r] = pJ[co[r] + dxe];
                }
            }
            rows_stats(vI, eI, lane, gxI[s], gyI[s], bI[s]);
            rows_stats(vJ, eJ, lane, gxJ[s], gyJ[s], bJ[s]);
        }
    }

    float acc = 0.0f;
    const float* mp = M + (size_t)z0 * NXY + yb * NX + x;

    // ZCHUNK steps, 4 per loop iter (2-slot phase repeats every 2 steps)
    for (int kb = 0; kb < ZCHUNK; kb += 4) {
        STEP(0, 1, kb + 0)
        STEP(1, 0, kb + 1)
        STEP(0, 1, kb + 2)
        STEP(1, 0, kb + 3)
    }

    // Block reduction
#pragma unroll
    for (int off = 16; off > 0; off >>= 1)
        acc += __shfl_xor_sync(FULLMASK, acc, off);
    if (lane == 0) warp_sums[wy] = acc;
    __syncthreads();

    if (tid == 0) {
        float v = warp_sums[0] + warp_sums[1] + warp_sums[2] + warp_sums[3];
        atomicAdd(&g_acc, (double)v);
        __threadfence();
        unsigned prev = atomicAdd(&g_done, 1u);
        if (prev == NBLOCKS - 1) {
            // All other blocks' g_acc adds are fenced before their g_done
            // increments, so an atomic read here sees the full sum.
            double tot = atomicAdd(&g_acc, 0.0);
            out[0] = (float)(tot * (1.0 / (double)((long long)NX * NY * NZ)));
            g_acc = 0.0;       // reset for next replay (deterministic)
            __threadfence();
            g_done = 0;
        }
    }
}

extern "C" void kernel_launch(void* const* d_in, const int* in_sizes, int n_in,
                              void* d_out, int out_size) {
    const float* I = (const float*)d_in[0];
    const float* J = (const float*)d_in[1];
    const float* M = (const float*)d_in[2];
    float* out = (float*)d_out;

    dim3 block(32, WYD, 1);
    dim3 grid(GXB, GYB, GZB);   // 6 x 24 x 6 = 864 CTAs
    ngf_kernel<<<grid, block>>>(I, J, M, out);
}

// round 11
// speedup vs baseline: 1.6021x; 1.2119x over previous
#include <cuda_runtime.h>
#include <cuda_bf16.h>

#define NX 192
#define NY 192
#define NZ 192
#define NXY (NX * NY)

#define VEC 2                    // float2 per thread in x
#define SEGW (32 * VEC)          // 64 x per warp
#define WYD 4                    // 4 warps/CTA, 1 y-row each
#define NTHREADS 128
#define ZCHUNK 32                // multiple of 4 (4-step unroll, 2-phase slots)
#define GXB (NX / SEGW)          // 3
#define GYB (NY / WYD)           // 48
#define GZB (NZ / ZCHUNK)        // 6
#define NBLOCKS (GXB * GYB * GZB) // 864 (single wave at 6 CTAs/SM)

#define FULLMASK 0xFFFFFFFFu

__device__ double g_acc = 0.0;
__device__ unsigned int g_done = 0;

// From preloaded row float2 v[3] (+ edge scalars e[3] for lanes 0/31),
// compute this thread's 2-element plane stats:
//   gx = sum_dy [v(x+1)-v(x-1)], gy = rowsum(y+1)-rowsum(y-1), b = 3x3 box
__device__ __forceinline__ void rows_stats(
    const float2* __restrict__ v, const float* __restrict__ e, int lane,
    float& gx0, float& gx1, float& gy0, float& gy1, float& b0, float& b1)
{
    float h0[3], h1[3], d0s = 0.f, d1s = 0.f;
#pragma unroll
    for (int r = 0; r < 3; ++r) {
        float l  = __shfl_up_sync(FULLMASK, v[r].y, 1);
        float rr = __shfl_down_sync(FULLMASK, v[r].x, 1);
        if (lane == 0)  l  = e[r];
        if (lane == 31) rr = e[r];
        float s = v[r].x + v[r].y;
        h0[r] = l + s;
        h1[r] = s + rr;
        d0s += v[r].y - l;
        d1s += rr - v[r].x;
    }
    gx0 = d0s;
    gx1 = d1s;
    gy0 = h0[2] - h0[0];
    gy1 = h1[2] - h1[0];
    b0  = h0[0] + h0[1] + h0[2];
    b1  = h1[0] + h1[1] + h1[2];
}

// One z-step for output plane z0+kk. Slot `o` = stats(z-1), `m` = stats(z).
// ALL loads (I rows, J rows, edge scalars, mask) are issued up front so the
// LSU has the full batch in flight before the shuffle/math chain starts.
#define STEP(o, m, kk)                                                        \
    {                                                                         \
        int zq = z0 + (kk) + 1;                                               \
        int gz = zq > NZ - 1 ? NZ - 1 : zq;                                   \
        size_t zoff = (size_t)gz * NXY;                                       \
        const float* pI = I + zoff;                                           \
        const float* pJ = J + zoff;                                           \
        float2 vI[3], vJ[3];                                                  \
        float  eI[3], eJ[3];                                                  \
        _Pragma("unroll")                                                     \
        for (int r = 0; r < 3; ++r)                                           \
            vI[r] = *reinterpret_cast<const float2*>(pI + co[r]);             \
        _Pragma("unroll")                                                     \
        for (int r = 0; r < 3; ++r)                                           \
            vJ[r] = *reinterpret_cast<const float2*>(pJ + co[r]);             \
        float2 m2 = *reinterpret_cast<const float2*>(mp);                     \
        if (edge) {                                                           \
            _Pragma("unroll")                                                 \
            for (int r = 0; r < 3; ++r) {                                     \
                eI[r] = pI[co[r] + dxe];                                      \
                eJ[r] = pJ[co[r] + dxe];                                      \
            }                                                                 \
        }                                                                     \
        float ngxI0, ngxI1, ngyI0, ngyI1, nbI0, nbI1;                         \
        float ngxJ0, ngxJ1, ngyJ0, ngyJ1, nbJ0, nbJ1;                         \
        rows_stats(vI, eI, lane, ngxI0, ngxI1, ngyI0, ngyI1, nbI0, nbI1);     \
        rows_stats(vJ, eJ, lane, ngxJ0, ngxJ1, ngyJ0, ngyJ1, nbJ0, nbJ1);     \
        {                                                                     \
            float Ix = gxI[o][0] + gxI[m][0] + ngxI0;                         \
            float Iy = gyI[o][0] + gyI[m][0] + ngyI0;                         \
            float Iz = nbI0 - bI[o][0];                                       \
            float Jx = gxJ[o][0] + gxJ[m][0] + ngxJ0;                         \
            float Jy = gyJ[o][0] + gyJ[m][0] + ngyJ0;                         \
            float Jz = nbJ0 - bJ[o][0];                                       \
            float ssi  = fmaf(Ix, Ix, fmaf(Iy, Iy, Iz * Iz));                 \
            float ssj  = fmaf(Jx, Jx, fmaf(Jy, Jy, Jz * Jz));                 \
            float sdot = fmaf(Ix, Jx, fmaf(Iy, Jy, Iz * Jz));                 \
            float ngf  = __fdividef(sdot * sdot,                              \
                                    (ssi + 0.04f) * (ssj + 0.04f));           \
            acc = fmaf(1.0f - ngf, m2.x, acc);                                \
        }                                                                     \
        {                                                                     \
            float Ix = gxI[o][1] + gxI[m][1] + ngxI1;                         \
            float Iy = gyI[o][1] + gyI[m][1] + ngyI1;                         \
            float Iz = nbI1 - bI[o][1];                                       \
            float Jx = gxJ[o][1] + gxJ[m][1] + ngxJ1;                         \
            float Jy = gyJ[o][1] + gyJ[m][1] + ngyJ1;                         \
            float Jz = nbJ1 - bJ[o][1];                                       \
            float ssi  = fmaf(Ix, Ix, fmaf(Iy, Iy, Iz * Iz));                 \
            float ssj  = fmaf(Jx, Jx, fmaf(Jy, Jy, Jz * Jz));                 \
            float sdot = fmaf(Ix, Jx, fmaf(Iy, Jy, Iz * Jz));                 \
            float ngf  = __fdividef(sdot * sdot,                              \
                                    (ssi + 0.04f) * (ssj + 0.04f));           \
            acc = fmaf(1.0f - ngf, m2.y, acc);                                \
        }                                                                     \
        gxI[o][0] = ngxI0; gxI[o][1] = ngxI1;                                 \
        gyI[o][0] = ngyI0; gyI[o][1] = ngyI1;                                 \
        bI[o][0]  = nbI0;  bI[o][1]  = nbI1;                                  \
        gxJ[o][0] = ngxJ0; gxJ[o][1] = ngxJ1;                                 \
        gyJ[o][0] = ngyJ0; gyJ[o][1] = ngyJ1;                                 \
        bJ[o][0]  = nbJ0;  bJ[o][1]  = nbJ1;                                  \
        mp += NXY;                                                            \
    }

__global__ __launch_bounds__(NTHREADS, 6)
void ngf_kernel(const float* __restrict__ I,
                const float* __restrict__ J,
                const float* __restrict__ M,
                float* __restrict__ out)
{
    __shared__ float warp_sums[WYD];

    const int lane = threadIdx.x;
    const int wy   = threadIdx.y;
    const int tid  = wy * 32 + lane;
    const int seg  = blockIdx.x;
    const int x2   = seg * SEGW + lane * VEC;
    const int y    = blockIdx.y * WYD + wy;
    const int z0   = blockIdx.z * ZCHUNK;

    const bool edge = (lane == 0) || (lane == 31);
    // Edge-lane neighbor offset relative to this thread's float2 base:
    //   lane 0 : left neighbor p[-1], or p[0] (=v.x, the clamp) at x2==0
    //   lane 31: right neighbor p[2], or p[1] (=v.y, the clamp) at x2+2==NX
    int dxe = 0;
    if (lane == 0)  dxe = (x2 > 0) ? -1 : 0;
    if (lane == 31) dxe = (x2 + VEC < NX) ? 2 : 1;

    // Clamped (y-row*NX + x2) offsets, constant across z
    int co[3];
#pragma unroll
    for (int r = 0; r < 3; ++r) {
        int gy = y - 1 + r;
        gy = gy < 0 ? 0 : (gy > NY - 1 ? NY - 1 : gy);
        co[r] = gy * NX + x2;
    }

    // 2-slot rolling z-state: [0]/[1] alternate as (z-1)/(z) per step phase
    float gxI[2][VEC], gyI[2][VEC], bI[2][VEC];
    float gxJ[2][VEC], gyJ[2][VEC], bJ[2][VEC];

    // Prologue: plane z0-1 (clamped) -> slot 0, plane z0 -> slot 1
    {
        int gzm = z0 - 1 < 0 ? 0 : z0 - 1;
#pragma unroll
        for (int s = 0; s < 2; ++s) {
            size_t zoff = (size_t)(s == 0 ? gzm : z0) * NXY;
            const float* pI = I + zoff;
            const float* pJ = J + zoff;
            float2 vI[3], vJ[3];
            float  eI[3], eJ[3];
#pragma unroll
            for (int r = 0; r < 3; ++r) {
                vI[r] = *reinterpret_cast<const float2*>(pI + co[r]);
                vJ[r] = *reinterpret_cast<const float2*>(pJ + co[r]);
            }
            if (edge) {
#pragma unroll
                for (int r = 0; r < 3; ++r) {
                    eI[r] = pI[co[r] + dxe];
                    eJ[r] = pJ[co[r] + dxe];
                }
            }
            rows_stats(vI, eI, lane, gxI[s][0], gxI[s][1],
                       gyI[s][0], gyI[s][1], bI[s][0], bI[s][1]);
            rows_stats(vJ, eJ, lane, gxJ[s][0], gxJ[s][1],
                       gyJ[s][0], gyJ[s][1], bJ[s][0], bJ[s][1]);
        }
    }

    float acc = 0.0f;
    const float* mp = M + (size_t)z0 * NXY + co[1];  // co[1] == y*NX + x2

    // ZCHUNK steps, 4 per loop iter so ptxas can overlap the next step's
    // load batch with the current step's shuffle/math chain.
    for (int kb = 0; kb < ZCHUNK; kb += 4) {
        STEP(0, 1, kb + 0)
        STEP(1, 0, kb + 1)
        STEP(0, 1, kb + 2)
        STEP(1, 0, kb + 3)
    }

    // Block reduction
#pragma unroll
    for (int off = 16; off > 0; off >>= 1)
        acc += __shfl_xor_sync(FULLMASK, acc, off);
    if (lane == 0) warp_sums[wy] = acc;
    __syncthreads();

    if (tid == 0) {
        float v = warp_sums[0] + warp_sums[1] + warp_sums[2] + warp_sums[3];
        atomicAdd(&g_acc, (double)v);
        __threadfence();
        unsigned prev = atomicAdd(&g_done, 1u);
        if (prev == NBLOCKS - 1) {
            // All other blocks' g_acc adds are fenced before their g_done
            // increments, so an atomic read here sees the full sum.
            double tot = atomicAdd(&g_acc, 0.0);
            out[0] = (float)(tot * (1.0 / (double)((long long)NX * NY * NZ)));
            g_acc = 0.0;       // reset for next replay (deterministic)
            __threadfence();
            g_done = 0;
        }
    }
}

extern "C" void kernel_launch(void* const* d_in, const int* in_sizes, int n_in,
                              void* d_out, int out_size) {
    const float* I = (const float*)d_in[0];
    const float* J = (const float*)d_in[1];
    const float* M = (const float*)d_in[2];
    float* out = (float*)d_out;

    dim3 block(32, WYD, 1);
    dim3 grid(GXB, GYB, GZB);   // 3 x 48 x 6 = 864 CTAs
    ngf_kernel<<<grid, block>>>(I, J, M, out);
}